// round 15
// baseline (speedup 1.0000x reference)
#include <cuda_runtime.h>
#include <cuda_bf16.h>
#include <math.h>
#include <stdint.h>

#define BB 16
#define L  2048
#define D  128
#define DV 128
#define EPSV 1e-12f
#define BL (BB * L)
#define LW (L / 32)

#define PITCHB 272                 // q/k smem row pitch (128 bf16 + pad)
#define TILEB  (128 * PITCHB)      // 34816 B per 128x128 bf16 tile
#define KCHUNKB (64 * PITCHB)      // 17408 B per 64-row k chunk
#define VPITCH 144                 // v chunk row pitch (64 bf16 + pad)
#define VTILE  (128 * VPITCH)      // 18432 B per 128d x 64j v chunk
#define SMEM_K1 (2 * TILEB + 2 * KCHUNKB)   // 104448
#define SMEM_K5 (2 * TILEB + 2 * VTILE)     // 106496

// ---- device scratch ----
__device__ float g_rps[8 * BL];    // row-sum partials
__device__ float g_cps[16 * BL];   // col-sum partials
__device__ uint32_t g_mbits[(size_t)BB * L * LW];
__device__ __nv_bfloat16 g_qh[BB * L * D], g_ql[BB * L * D];
__device__ __nv_bfloat16 g_kh[BB * L * D], g_kl[BB * L * D];
__device__ __nv_bfloat16 g_vTh[BB * D * L], g_vTl[BB * D * L]; // [b][d][j]
__device__ float g_opart[2 * (size_t)BB * L * DV];

// ================= helpers =================
__device__ __forceinline__ uint32_t smem_u32(const void* p) {
    uint32_t a;
    asm("{ .reg .u64 t; cvta.to.shared.u64 t, %1; cvt.u32.u64 %0, t; }" : "=r"(a) : "l"(p));
    return a;
}
__device__ __forceinline__ void ldm_x4(uint32_t* r, uint32_t addr) {
    asm volatile("ldmatrix.sync.aligned.m8n8.x4.shared.b16 {%0,%1,%2,%3}, [%4];"
        : "=r"(r[0]), "=r"(r[1]), "=r"(r[2]), "=r"(r[3]) : "r"(addr));
}
__device__ __forceinline__ void mma_bf16(float* c, const uint32_t* a, const uint32_t* b) {
    asm volatile("mma.sync.aligned.m16n8k16.row.col.f32.bf16.bf16.f32 "
        "{%0,%1,%2,%3}, {%4,%5,%6,%7}, {%8,%9}, {%0,%1,%2,%3};"
        : "+f"(c[0]), "+f"(c[1]), "+f"(c[2]), "+f"(c[3])
        : "r"(a[0]), "r"(a[1]), "r"(a[2]), "r"(a[3]), "r"(b[0]), "r"(b[1]));
}
#define CP16(dst, src) asm volatile("cp.async.cg.shared.global [%0], [%1], 16;" :: "r"(dst), "l"(src))
#define CP_COMMIT()    asm volatile("cp.async.commit_group;" ::: "memory")
#define CP_WAIT0()     asm volatile("cp.async.wait_group 0;" ::: "memory")

__device__ __forceinline__ void split4(float4 a, uint2& h, uint2& l) {
    __nv_bfloat16 h0 = __float2bfloat16(a.x), h1 = __float2bfloat16(a.y);
    __nv_bfloat16 h2 = __float2bfloat16(a.z), h3 = __float2bfloat16(a.w);
    float l0 = a.x - __bfloat162float(h0), l1 = a.y - __bfloat162float(h1);
    float l2 = a.z - __bfloat162float(h2), l3 = a.w - __bfloat162float(h3);
    __nv_bfloat162 ph0{h0, h1}, ph1{h2, h3};
    __nv_bfloat162 pl0{__float2bfloat16(l0), __float2bfloat16(l1)};
    __nv_bfloat162 pl1{__float2bfloat16(l2), __float2bfloat16(l3)};
    h = make_uint2(*reinterpret_cast<uint32_t*>(&ph0), *reinterpret_cast<uint32_t*>(&ph1));
    l = make_uint2(*reinterpret_cast<uint32_t*>(&pl0), *reinterpret_cast<uint32_t*>(&pl1));
}

// ============================================================
// K0: fused split of q,k ; v^T ; mask bitmap.  grid 16384.
// ============================================================
__global__ __launch_bounds__(256) void k_split_all(
    const float* __restrict__ q, const float* __restrict__ kmat,
    const float* __restrict__ v, const float* __restrict__ M)
{
    __shared__ float tile[32][33];
    const int tid = threadIdx.x;
    if (blockIdx.x < 4096) {
        const size_t i = ((size_t)blockIdx.x * 256 + tid) * 4;
        uint2 h, l;
        split4(*reinterpret_cast<const float4*>(q + i), h, l);
        *reinterpret_cast<uint2*>(&g_qh[i]) = h;
        *reinterpret_cast<uint2*>(&g_ql[i]) = l;
        split4(*reinterpret_cast<const float4*>(kmat + i), h, l);
        *reinterpret_cast<uint2*>(&g_kh[i]) = h;
        *reinterpret_cast<uint2*>(&g_kl[i]) = l;
    } else if (blockIdx.x < 8192) {
        const int vb = blockIdx.x - 4096;
        const int jt = vb & 63, dt = (vb >> 6) & 3, b = vb >> 8;
        const int j0 = jt * 32, d0 = dt * 32;
        const int tx = tid & 31, ty = tid >> 5;
#pragma unroll
        for (int i = 0; i < 4; i++)
            tile[ty + i * 8][tx] = v[((size_t)b * L + j0 + ty + i * 8) * DV + d0 + tx];
        __syncthreads();
#pragma unroll
        for (int i = 0; i < 4; i++) {
            float x = tile[tx][ty + i * 8];
            __nv_bfloat16 h = __float2bfloat16(x);
            __nv_bfloat16 lo = __float2bfloat16(x - __bfloat162float(h));
            size_t idx = ((size_t)b * D + d0 + ty + i * 8) * L + j0 + tx;
            g_vTh[idx] = h;
            g_vTl[idx] = lo;
        }
    } else {
        const size_t warpId = ((size_t)(blockIdx.x - 8192) * 256 + tid) >> 5;
        const int lane = tid & 31;
        const size_t base = warpId * 1024;
        uint32_t myword = 0;
#pragma unroll
        for (int i = 0; i < 32; i++) {
            float mv = __ldcs(M + base + (size_t)i * 32 + lane);
            uint32_t bt = __ballot_sync(0xFFFFFFFFu, mv != 0.0f);
            if (lane == i) myword = bt;
        }
        g_mbits[warpId * 32 + lane] = myword;
    }
}

// ============================================================
// K1: fused E = mask*exp(q k^T) + row/col partial sums.
// grid (4 jt4, 16 it, B), block 256, 2 CTAs/SM, 64-col chunks.
// (round-7 passing version)
// ============================================================
__global__ __launch_bounds__(256, 2) void k_qkE(float* __restrict__ E)
{
    extern __shared__ __align__(16) char smem[];
    __shared__ float colacc[4][512];

    const int tid = threadIdx.x;
    const int w = tid >> 5, lane = tid & 31;
    const int b = blockIdx.z;
    const int i0 = blockIdx.y * 128;
    const int jt4 = blockIdx.x;

    const uint32_t bq  = smem_u32(smem);
    const uint32_t bql = bq + TILEB;
    const uint32_t bk  = bq + 2 * TILEB;
    const uint32_t bkl = bk + KCHUNKB;

    const __nv_bfloat16* qh = g_qh + ((size_t)b * L + i0) * D;
    const __nv_bfloat16* ql = g_ql + ((size_t)b * L + i0) * D;
    const __nv_bfloat16* khB = g_kh + (size_t)b * L * D;
    const __nv_bfloat16* klB = g_kl + (size_t)b * L * D;

#pragma unroll
    for (int u = 0; u < 8; u++) ((float*)colacc)[u * 256 + tid] = 0.f;

#pragma unroll
    for (int u = 0; u < 8; u++) {
        int f = u * 256 + tid;
        int row = f >> 4, c = f & 15;
        uint32_t so = (uint32_t)row * PITCHB + (uint32_t)c * 16;
        CP16(bq  + so, qh + (size_t)row * D + c * 8);
        CP16(bql + so, ql + (size_t)row * D + c * 8);
    }
    {
        const int j0 = jt4 * 512;
#pragma unroll
        for (int u = 0; u < 4; u++) {
            int f = u * 256 + tid;
            int row = f >> 4, c = f & 15;
            uint32_t so = (uint32_t)row * PITCHB + (uint32_t)c * 16;
            CP16(bk  + so, khB + ((size_t)(j0 + row)) * D + c * 8);
            CP16(bkl + so, klB + ((size_t)(j0 + row)) * D + c * 8);
        }
    }
    CP_COMMIT();

    const int wr = w & 3, wc = w >> 2;
    const int tr = lane >> 2, tc = lane & 3;
    float rowsum[4] = {0.f, 0.f, 0.f, 0.f};
    const uint32_t* MB = g_mbits + ((size_t)b * L + i0) * LW;

    for (int jl = 0; jl < 8; jl++) {
        const int j0 = jt4 * 512 + jl * 64;
        CP_WAIT0();
        __syncthreads();

        uint2 mb[4];
        {
            const int wbase = j0 >> 5;
#pragma unroll
            for (int u = 0; u < 4; u++) {
                int row = wr * 32 + u * 8 + tr;
                mb[u] = *reinterpret_cast<const uint2*>(MB + (size_t)row * LW + wbase);
            }
        }

        float acc[2][4][4];
#pragma unroll
        for (int mt = 0; mt < 2; mt++)
#pragma unroll
            for (int nt = 0; nt < 4; nt++)
#pragma unroll
                for (int u = 0; u < 4; u++) acc[mt][nt][u] = 0.f;

#pragma unroll
        for (int ks = 0; ks < 8; ks++) {
            const uint32_t kb0 = ks * 32;
            uint32_t Ah[2][4], Al[2][4], Bh[2][4], Bl[2][4];
            uint32_t arow = (uint32_t)(wr * 32 + (lane & 15)) * PITCHB + kb0 + ((lane >> 4) << 4);
#pragma unroll
            for (int mt = 0; mt < 2; mt++) {
                uint32_t ad = arow + mt * 16 * PITCHB;
                ldm_x4(Ah[mt], bq  + ad);
                ldm_x4(Al[mt], bql + ad);
            }
            uint32_t brow = (uint32_t)(wc * 32 + (lane & 7) + ((lane >> 4) << 3)) * PITCHB
                          + kb0 + (((lane >> 3) & 1) << 4);
#pragma unroll
            for (int ntp = 0; ntp < 2; ntp++) {
                uint32_t bd = brow + ntp * 16 * PITCHB;
                ldm_x4(Bh[ntp], bk  + bd);
                ldm_x4(Bl[ntp], bkl + bd);
            }
#pragma unroll
            for (int mt = 0; mt < 2; mt++)
#pragma unroll
                for (int ntp = 0; ntp < 2; ntp++) {
                    mma_bf16(acc[mt][2 * ntp],     Ah[mt], &Bh[ntp][0]);
                    mma_bf16(acc[mt][2 * ntp + 1], Ah[mt], &Bh[ntp][2]);
                    mma_bf16(acc[mt][2 * ntp],     Al[mt], &Bh[ntp][0]);
                    mma_bf16(acc[mt][2 * ntp + 1], Al[mt], &Bh[ntp][2]);
                    mma_bf16(acc[mt][2 * ntp],     Ah[mt], &Bl[ntp][0]);
                    mma_bf16(acc[mt][2 * ntp + 1], Ah[mt], &Bl[ntp][2]);
                }
        }
        __syncthreads();

        if (jl < 7) {
            const int jn = j0 + 64;
#pragma unroll
            for (int u = 0; u < 4; u++) {
                int f = u * 256 + tid;
                int row = f >> 4, c = f & 15;
                uint32_t so = (uint32_t)row * PITCHB + (uint32_t)c * 16;
                CP16(bk  + so, khB + ((size_t)(jn + row)) * D + c * 8);
                CP16(bkl + so, klB + ((size_t)(jn + row)) * D + c * 8);
            }
            CP_COMMIT();
        }

        float* Eb = E + ((size_t)b * L + i0) * L + j0;
        float cs0[4], cs1[4];
#pragma unroll
        for (int nt = 0; nt < 4; nt++) { cs0[nt] = 0.f; cs1[nt] = 0.f; }
#pragma unroll
        for (int mt = 0; mt < 2; mt++)
#pragma unroll
            for (int nt = 0; nt < 4; nt++) {
                int r = wr * 32 + mt * 16 + tr;
                int cc = wc * 32 + nt * 8 + tc * 2;
                uint32_t w0 = (cc < 32) ? mb[mt * 2].x     : mb[mt * 2].y;
                uint32_t w1 = (cc < 32) ? mb[mt * 2 + 1].x : mb[mt * 2 + 1].y;
                int sh = cc & 31;
                float e0 = ((w0 >> sh) & 1u)       ? __expf(acc[mt][nt][0]) : 0.f;
                float e1 = ((w0 >> (sh + 1)) & 1u) ? __expf(acc[mt][nt][1]) : 0.f;
                float e2 = ((w1 >> sh) & 1u)       ? __expf(acc[mt][nt][2]) : 0.f;
                float e3 = ((w1 >> (sh + 1)) & 1u) ? __expf(acc[mt][nt][3]) : 0.f;
                __stcs(reinterpret_cast<float2*>(Eb + (size_t)r * L + cc),       make_float2(e0, e1));
                __stcs(reinterpret_cast<float2*>(Eb + (size_t)(r + 8) * L + cc), make_float2(e2, e3));
                rowsum[mt * 2]     += e0 + e1;
                rowsum[mt * 2 + 1] += e2 + e3;
                cs0[nt] += e0 + e2;
                cs1[nt] += e1 + e3;
            }
#pragma unroll
        for (int nt = 0; nt < 4; nt++) {
            cs0[nt] += __shfl_xor_sync(0xFFFFFFFFu, cs0[nt], 4);
            cs0[nt] += __shfl_xor_sync(0xFFFFFFFFu, cs0[nt], 8);
            cs0[nt] += __shfl_xor_sync(0xFFFFFFFFu, cs0[nt], 16);
            cs1[nt] += __shfl_xor_sync(0xFFFFFFFFu, cs1[nt], 4);
            cs1[nt] += __shfl_xor_sync(0xFFFFFFFFu, cs1[nt], 8);
            cs1[nt] += __shfl_xor_sync(0xFFFFFFFFu, cs1[nt], 16);
        }
#pragma unroll
        for (int nt = 0; nt < 4; nt++) {
            if (tr == nt) {
                int c = jl * 64 + wc * 32 + nt * 8 + tc * 2;
                colacc[wr][c]     += cs0[nt];
                colacc[wr][c + 1] += cs1[nt];
            }
        }
    }

#pragma unroll
    for (int u = 0; u < 4; u++) {
        rowsum[u] += __shfl_xor_sync(0xFFFFFFFFu, rowsum[u], 1);
        rowsum[u] += __shfl_xor_sync(0xFFFFFFFFu, rowsum[u], 2);
    }
    if (tc == 0) {
        float* rp = &g_rps[(size_t)(jt4 * 2 + wc) * BL + (size_t)b * L + i0 + wr * 32 + tr];
        rp[0] = rowsum[0]; rp[8] = rowsum[1]; rp[16] = rowsum[2]; rp[24] = rowsum[3];
    }
    __syncthreads();
    {
        int c = tid * 2;
        float s0 = colacc[0][c] + colacc[1][c] + colacc[2][c] + colacc[3][c];
        float s1 = colacc[0][c + 1] + colacc[1][c + 1] + colacc[2][c + 1] + colacc[3][c + 1];
        float* cp = &g_cps[(size_t)blockIdx.y * BL + (size_t)b * L + jt4 * 512 + c];
        cp[0] = s0; cp[1] = s1;
    }
}

// ============================================================
// K5: prologue merges partials; gated = (E*rdi)*(E*cdi) in place;
// out partial = gated @ v.  grid (16 it, 2 ks, B), block 256, 2 CTAs/SM.
// Gate phase split by j-halves so the hc=1 v-chunk load is hidden
// under gate half1 instead of exposed between the two mma phases.
// ============================================================
__global__ __launch_bounds__(256, 2) void k_gate_out_mma(float* __restrict__ Eg)
{
    extern __shared__ __align__(16) char smem[];
    __shared__ float F_s[128];
    __shared__ float cd_all[1024];

    const int tid = threadIdx.x;
    const int w = tid >> 5, lane = tid & 31;
    const int b = blockIdx.z;
    const int i0 = blockIdx.x * 128;
    const int ks = blockIdx.y;

    const uint32_t bg  = smem_u32(smem);
    const uint32_t bgl = bg + TILEB;
    const uint32_t bv  = bg + 2 * TILEB;
    const uint32_t bvl = bv + VTILE;

    // prologue: merge row/col partials for this CTA's spans
    if (tid < 128) {
        float rs = 0.f;
#pragma unroll
        for (int p = 0; p < 8; p++) rs += g_rps[(size_t)p * BL + (size_t)b * L + i0 + tid];
        F_s[tid] = 1.0f / (rs + EPSV);
    }
#pragma unroll
    for (int u = 0; u < 4; u++) {
        int col = u * 256 + tid;
        float cs = 0.f;
#pragma unroll
        for (int p = 0; p < 16; p++) cs += g_cps[(size_t)p * BL + (size_t)b * L + ks * 1024 + col];
        cd_all[col] = 1.0f / (cs + EPSV);
    }

    const int wr = w & 3, wc = w >> 2;
    const int tr = lane >> 2, tc = lane & 3;
    float acc[2][8][4];
#pragma unroll
    for (int mt = 0; mt < 2; mt++)
#pragma unroll
        for (int nt = 0; nt < 8; nt++)
#pragma unroll
            for (int u = 0; u < 4; u++) acc[mt][nt][u] = 0.f;

    float* Eb = Eg + ((size_t)b * L + i0) * L;
    const __nv_bfloat16* vhB = g_vTh + (size_t)b * D * L;
    const __nv_bfloat16* vlB = g_vTl + (size_t)b * D * L;

    __syncthreads();   // prologue visible

    for (int jc = 0; jc < 8; jc++) {
        const int j0 = ks * 1024 + jc * 128;

        for (int hc = 0; hc < 2; hc++) {
            // issue v chunk hc (overlaps gate half hc)
            {
                const int jv = j0 + hc * 64;
#pragma unroll
                for (int u = 0; u < 4; u++) {
                    int f = u * 256 + tid;
                    int row = f >> 3, c = f & 7;
                    uint32_t so = (uint32_t)row * VPITCH + (uint32_t)c * 16;
                    CP16(bv  + so, vhB + (size_t)row * L + jv + c * 8);
                    CP16(bvl + so, vlB + (size_t)row * L + jv + c * 8);
                }
                CP_COMMIT();
            }

            // gate half hc: 128 rows x 64 cols [j0+hc*64 .. +64)
#pragma unroll
            for (int it = 0; it < 8; it++) {
                int f = it * 256 + tid;
                int row = f >> 4, c4 = f & 15;
                size_t off = (size_t)row * L + j0 + hc * 64 + c4 * 4;
                float4 e = __ldcs(reinterpret_cast<const float4*>(Eb + off));
                float4 cd = *reinterpret_cast<const float4*>(&cd_all[jc * 128 + hc * 64 + c4 * 4]);
                float Fi = F_s[row];
                float4 g;
                g.x = (e.x * Fi) * (e.x * cd.x);
                g.y = (e.y * Fi) * (e.y * cd.y);
                g.z = (e.z * Fi) * (e.z * cd.z);
                g.w = (e.w * Fi) * (e.w * cd.w);
                __stcs(reinterpret_cast<float4*>(Eb + off), g);
                uint2 h, l;
                split4(g, h, l);
                uint32_t so = (uint32_t)row * PITCHB + (uint32_t)(hc * 128 + c4 * 8);
                *reinterpret_cast<uint2*>(smem + so)         = h;
                *reinterpret_cast<uint2*>(smem + TILEB + so) = l;
            }

            CP_WAIT0();
            __syncthreads();   // v chunk hc + gate half hc visible

#pragma unroll
            for (int ksv = 0; ksv < 4; ksv++) {
                uint32_t Ah[2][4], Al[2][4], Bh[4][4], Bl[4][4];
                uint32_t arow = (uint32_t)(wr * 32 + (lane & 15)) * PITCHB
                              + hc * 128 + ksv * 32 + ((lane >> 4) << 4);
#pragma unroll
                for (int mt = 0; mt < 2; mt++) {
                    uint32_t ad = arow + mt * 16 * PITCHB;
                    ldm_x4(Ah[mt], bg  + ad);
                    ldm_x4(Al[mt], bgl + ad);
                }
                uint32_t brow = (uint32_t)(wc * 64 + (lane & 7) + ((lane >> 4) << 3)) * VPITCH
                              + ksv * 32 + (((lane >> 3) & 1) << 4);
#pragma unroll
                for (int ntp = 0; ntp < 4; ntp++) {
                    uint32_t bd = brow + ntp * 16 * VPITCH;
                    ldm_x4(Bh[ntp], bv  + bd);
                    ldm_x4(Bl[ntp], bvl + bd);
                }
#pragma unroll
                for (int mt = 0; mt < 2; mt++)
#pragma unroll
                    for (int ntp = 0; ntp < 4; ntp++) {
                        mma_bf16(acc[mt][2 * ntp],     Ah[mt], &Bh[ntp][0]);
                        mma_bf16(acc[mt][2 * ntp + 1], Ah[mt], &Bh[ntp][2]);
                        mma_bf16(acc[mt][2 * ntp],     Al[mt], &Bh[ntp][0]);
                        mma_bf16(acc[mt][2 * ntp + 1], Al[mt], &Bh[ntp][2]);
                        mma_bf16(acc[mt][2 * ntp],     Ah[mt], &Bl[ntp][0]);
                        mma_bf16(acc[mt][2 * ntp + 1], Ah[mt], &Bl[ntp][2]);
                    }
            }
            __syncthreads();   // v buffer + g half reusable
        }
    }

    // out partial: direct float2 stores
    float* op = g_opart + (((size_t)ks * BB + b) * L + i0) * DV;
#pragma unroll
    for (int mt = 0; mt < 2; mt++)
#pragma unroll
        for (int nt = 0; nt < 8; nt++) {
            int r = wr * 32 + mt * 16 + tr;
            int cc = wc * 64 + nt * 8 + tc * 2;
            *reinterpret_cast<float2*>(op + (size_t)r * DV + cc) =
                make_float2(acc[mt][nt][0], acc[mt][nt][1]);
            *reinterpret_cast<float2*>(op + (size_t)(r + 8) * DV + cc) =
                make_float2(acc[mt][nt][2], acc[mt][nt][3]);
        }
}

// K6: reduce 2 output partials
__global__ __launch_bounds__(256) void k_out_reduce(float* __restrict__ out)
{
    const size_t i = ((size_t)blockIdx.x * 256 + threadIdx.x) * 4;
    const size_t n = (size_t)BB * L * DV;
    float4 a = *reinterpret_cast<const float4*>(&g_opart[i]);
    float4 bq = *reinterpret_cast<const float4*>(&g_opart[n + i]);
    float4 r;
    r.x = a.x + bq.x; r.y = a.y + bq.y; r.z = a.z + bq.z; r.w = a.w + bq.w;
    *reinterpret_cast<float4*>(out + i) = r;
}

// ============================================================
extern "C" void kernel_launch(void* const* d_in, const int* in_sizes, int n_in,
                              void* d_out, int out_size)
{
    const float* q    = (const float*)d_in[0];
    const float* kmat = (const float*)d_in[1];
    const float* v    = (const float*)d_in[2];
    const float* mask = (const float*)d_in[3];

    float* out   = (float*)d_out;
    float* gated = out + (size_t)BB * L * DV;   // E -> gated in place

    cudaFuncSetAttribute(k_qkE,          cudaFuncAttributeMaxDynamicSharedMemorySize, SMEM_K1);
    cudaFuncSetAttribute(k_gate_out_mma, cudaFuncAttributeMaxDynamicSharedMemorySize, SMEM_K5);

    k_split_all<<<16384, 256>>>(q, kmat, v, mask);                 // 1
    k_qkE<<<dim3(4, 16, BB), 256, SMEM_K1>>>(gated);               // 2
    k_gate_out_mma<<<dim3(16, 2, BB), 256, SMEM_K5>>>(gated);      // 3
    k_out_reduce<<<(BB * L * DV) / 1024, 256>>>(out);              // 4
}

// round 16
// speedup vs baseline: 1.0211x; 1.0211x over previous
#include <cuda_runtime.h>
#include <cuda_bf16.h>
#include <math.h>
#include <stdint.h>

#define BB 16
#define L  2048
#define D  128
#define DV 128
#define EPSV 1e-12f
#define BL (BB * L)
#define LW (L / 32)

#define PITCHB 272                 // q/k smem row pitch (128 bf16 + pad)
#define TILEB  (128 * PITCHB)      // 34816 B per 128x128 bf16 tile
#define KCHUNKB (64 * PITCHB)      // 17408 B per 64-row k chunk
#define VPITCH 144                 // v chunk row pitch (64 bf16 + pad)
#define VTILE  (128 * VPITCH)      // 18432 B per 128d x 64j v chunk
#define SMEM_K1 (2 * TILEB + 2 * KCHUNKB)   // 104448
#define SMEM_K5 (2 * TILEB + 2 * VTILE)     // 106496

// ---- device scratch ----
__device__ float g_rps[8 * BL];    // row-sum partials
__device__ float g_cps[16 * BL];   // col-sum partials
__device__ uint32_t g_mbits[(size_t)BB * L * LW];
__device__ __nv_bfloat16 g_qh[BB * L * D], g_ql[BB * L * D];
__device__ __nv_bfloat16 g_kh[BB * L * D], g_kl[BB * L * D];
__device__ __nv_bfloat16 g_vTh[BB * D * L], g_vTl[BB * D * L]; // [b][d][j]
__device__ float g_opart[(size_t)BB * L * DV];   // ks=1 partial only

// ================= helpers =================
__device__ __forceinline__ uint32_t smem_u32(const void* p) {
    uint32_t a;
    asm("{ .reg .u64 t; cvta.to.shared.u64 t, %1; cvt.u32.u64 %0, t; }" : "=r"(a) : "l"(p));
    return a;
}
__device__ __forceinline__ void ldm_x4(uint32_t* r, uint32_t addr) {
    asm volatile("ldmatrix.sync.aligned.m8n8.x4.shared.b16 {%0,%1,%2,%3}, [%4];"
        : "=r"(r[0]), "=r"(r[1]), "=r"(r[2]), "=r"(r[3]) : "r"(addr));
}
__device__ __forceinline__ void mma_bf16(float* c, const uint32_t* a, const uint32_t* b) {
    asm volatile("mma.sync.aligned.m16n8k16.row.col.f32.bf16.bf16.f32 "
        "{%0,%1,%2,%3}, {%4,%5,%6,%7}, {%8,%9}, {%0,%1,%2,%3};"
        : "+f"(c[0]), "+f"(c[1]), "+f"(c[2]), "+f"(c[3])
        : "r"(a[0]), "r"(a[1]), "r"(a[2]), "r"(a[3]), "r"(b[0]), "r"(b[1]));
}
#define CP16(dst, src) asm volatile("cp.async.cg.shared.global [%0], [%1], 16;" :: "r"(dst), "l"(src))
#define CP_COMMIT()    asm volatile("cp.async.commit_group;" ::: "memory")
#define CP_WAIT0()     asm volatile("cp.async.wait_group 0;" ::: "memory")

__device__ __forceinline__ void split4(float4 a, uint2& h, uint2& l) {
    __nv_bfloat16 h0 = __float2bfloat16(a.x), h1 = __float2bfloat16(a.y);
    __nv_bfloat16 h2 = __float2bfloat16(a.z), h3 = __float2bfloat16(a.w);
    float l0 = a.x - __bfloat162float(h0), l1 = a.y - __bfloat162float(h1);
    float l2 = a.z - __bfloat162float(h2), l3 = a.w - __bfloat162float(h3);
    __nv_bfloat162 ph0{h0, h1}, ph1{h2, h3};
    __nv_bfloat162 pl0{__float2bfloat16(l0), __float2bfloat16(l1)};
    __nv_bfloat162 pl1{__float2bfloat16(l2), __float2bfloat16(l3)};
    h = make_uint2(*reinterpret_cast<uint32_t*>(&ph0), *reinterpret_cast<uint32_t*>(&ph1));
    l = make_uint2(*reinterpret_cast<uint32_t*>(&pl0), *reinterpret_cast<uint32_t*>(&pl1));
}

// ============================================================
// K0: fused split of q,k ; v^T ; mask bitmap.  grid 16384.
// ============================================================
__global__ __launch_bounds__(256) void k_split_all(
    const float* __restrict__ q, const float* __restrict__ kmat,
    const float* __restrict__ v, const float* __restrict__ M)
{
    __shared__ float tile[32][33];
    const int tid = threadIdx.x;
    if (blockIdx.x < 4096) {
        const size_t i = ((size_t)blockIdx.x * 256 + tid) * 4;
        uint2 h, l;
        split4(*reinterpret_cast<const float4*>(q + i), h, l);
        *reinterpret_cast<uint2*>(&g_qh[i]) = h;
        *reinterpret_cast<uint2*>(&g_ql[i]) = l;
        split4(*reinterpret_cast<const float4*>(kmat + i), h, l);
        *reinterpret_cast<uint2*>(&g_kh[i]) = h;
        *reinterpret_cast<uint2*>(&g_kl[i]) = l;
    } else if (blockIdx.x < 8192) {
        const int vb = blockIdx.x - 4096;
        const int jt = vb & 63, dt = (vb >> 6) & 3, b = vb >> 8;
        const int j0 = jt * 32, d0 = dt * 32;
        const int tx = tid & 31, ty = tid >> 5;
#pragma unroll
        for (int i = 0; i < 4; i++)
            tile[ty + i * 8][tx] = v[((size_t)b * L + j0 + ty + i * 8) * DV + d0 + tx];
        __syncthreads();
#pragma unroll
        for (int i = 0; i < 4; i++) {
            float x = tile[tx][ty + i * 8];
            __nv_bfloat16 h = __float2bfloat16(x);
            __nv_bfloat16 lo = __float2bfloat16(x - __bfloat162float(h));
            size_t idx = ((size_t)b * D + d0 + ty + i * 8) * L + j0 + tx;
            g_vTh[idx] = h;
            g_vTl[idx] = lo;
        }
    } else {
        const size_t warpId = ((size_t)(blockIdx.x - 8192) * 256 + tid) >> 5;
        const int lane = tid & 31;
        const size_t base = warpId * 1024;
        uint32_t myword = 0;
#pragma unroll
        for (int i = 0; i < 32; i++) {
            float mv = __ldcs(M + base + (size_t)i * 32 + lane);
            uint32_t bt = __ballot_sync(0xFFFFFFFFu, mv != 0.0f);
            if (lane == i) myword = bt;
        }
        g_mbits[warpId * 32 + lane] = myword;
    }
}

// ============================================================
// K1: fused E = mask*exp(q k^T) + row/col partial sums.
// grid (4 jt4, 16 it, B), block 256, 2 CTAs/SM, 64-col chunks.
// ============================================================
__global__ __launch_bounds__(256, 2) void k_qkE(float* __restrict__ E)
{
    extern __shared__ __align__(16) char smem[];
    __shared__ float colacc[4][512];

    const int tid = threadIdx.x;
    const int w = tid >> 5, lane = tid & 31;
    const int b = blockIdx.z;
    const int i0 = blockIdx.y * 128;
    const int jt4 = blockIdx.x;

    const uint32_t bq  = smem_u32(smem);
    const uint32_t bql = bq + TILEB;
    const uint32_t bk  = bq + 2 * TILEB;
    const uint32_t bkl = bk + KCHUNKB;

    const __nv_bfloat16* qh = g_qh + ((size_t)b * L + i0) * D;
    const __nv_bfloat16* ql = g_ql + ((size_t)b * L + i0) * D;
    const __nv_bfloat16* khB = g_kh + (size_t)b * L * D;
    const __nv_bfloat16* klB = g_kl + (size_t)b * L * D;

#pragma unroll
    for (int u = 0; u < 8; u++) ((float*)colacc)[u * 256 + tid] = 0.f;

#pragma unroll
    for (int u = 0; u < 8; u++) {
        int f = u * 256 + tid;
        int row = f >> 4, c = f & 15;
        uint32_t so = (uint32_t)row * PITCHB + (uint32_t)c * 16;
        CP16(bq  + so, qh + (size_t)row * D + c * 8);
        CP16(bql + so, ql + (size_t)row * D + c * 8);
    }
    {
        const int j0 = jt4 * 512;
#pragma unroll
        for (int u = 0; u < 4; u++) {
            int f = u * 256 + tid;
            int row = f >> 4, c = f & 15;
            uint32_t so = (uint32_t)row * PITCHB + (uint32_t)c * 16;
            CP16(bk  + so, khB + ((size_t)(j0 + row)) * D + c * 8);
            CP16(bkl + so, klB + ((size_t)(j0 + row)) * D + c * 8);
        }
    }
    CP_COMMIT();

    const int wr = w & 3, wc = w >> 2;
    const int tr = lane >> 2, tc = lane & 3;
    float rowsum[4] = {0.f, 0.f, 0.f, 0.f};
    const uint32_t* MB = g_mbits + ((size_t)b * L + i0) * LW;

    for (int jl = 0; jl < 8; jl++) {
        const int j0 = jt4 * 512 + jl * 64;
        CP_WAIT0();
        __syncthreads();

        uint2 mb[4];
        {
            const int wbase = j0 >> 5;
#pragma unroll
            for (int u = 0; u < 4; u++) {
                int row = wr * 32 + u * 8 + tr;
                mb[u] = *reinterpret_cast<const uint2*>(MB + (size_t)row * LW + wbase);
            }
        }

        float acc[2][4][4];
#pragma unroll
        for (int mt = 0; mt < 2; mt++)
#pragma unroll
            for (int nt = 0; nt < 4; nt++)
#pragma unroll
                for (int u = 0; u < 4; u++) acc[mt][nt][u] = 0.f;

#pragma unroll
        for (int ks = 0; ks < 8; ks++) {
            const uint32_t kb0 = ks * 32;
            uint32_t Ah[2][4], Al[2][4], Bh[2][4], Bl[2][4];
            uint32_t arow = (uint32_t)(wr * 32 + (lane & 15)) * PITCHB + kb0 + ((lane >> 4) << 4);
#pragma unroll
            for (int mt = 0; mt < 2; mt++) {
                uint32_t ad = arow + mt * 16 * PITCHB;
                ldm_x4(Ah[mt], bq  + ad);
                ldm_x4(Al[mt], bql + ad);
            }
            uint32_t brow = (uint32_t)(wc * 32 + (lane & 7) + ((lane >> 4) << 3)) * PITCHB
                          + kb0 + (((lane >> 3) & 1) << 4);
#pragma unroll
            for (int ntp = 0; ntp < 2; ntp++) {
                uint32_t bd = brow + ntp * 16 * PITCHB;
                ldm_x4(Bh[ntp], bk  + bd);
                ldm_x4(Bl[ntp], bkl + bd);
            }
#pragma unroll
            for (int mt = 0; mt < 2; mt++)
#pragma unroll
                for (int ntp = 0; ntp < 2; ntp++) {
                    mma_bf16(acc[mt][2 * ntp],     Ah[mt], &Bh[ntp][0]);
                    mma_bf16(acc[mt][2 * ntp + 1], Ah[mt], &Bh[ntp][2]);
                    mma_bf16(acc[mt][2 * ntp],     Al[mt], &Bh[ntp][0]);
                    mma_bf16(acc[mt][2 * ntp + 1], Al[mt], &Bh[ntp][2]);
                    mma_bf16(acc[mt][2 * ntp],     Ah[mt], &Bl[ntp][0]);
                    mma_bf16(acc[mt][2 * ntp + 1], Ah[mt], &Bl[ntp][2]);
                }
        }
        __syncthreads();

        if (jl < 7) {
            const int jn = j0 + 64;
#pragma unroll
            for (int u = 0; u < 4; u++) {
                int f = u * 256 + tid;
                int row = f >> 4, c = f & 15;
                uint32_t so = (uint32_t)row * PITCHB + (uint32_t)c * 16;
                CP16(bk  + so, khB + ((size_t)(jn + row)) * D + c * 8);
                CP16(bkl + so, klB + ((size_t)(jn + row)) * D + c * 8);
            }
            CP_COMMIT();
        }

        float* Eb = E + ((size_t)b * L + i0) * L + j0;
        float cs0[4], cs1[4];
#pragma unroll
        for (int nt = 0; nt < 4; nt++) { cs0[nt] = 0.f; cs1[nt] = 0.f; }
#pragma unroll
        for (int mt = 0; mt < 2; mt++)
#pragma unroll
            for (int nt = 0; nt < 4; nt++) {
                int r = wr * 32 + mt * 16 + tr;
                int cc = wc * 32 + nt * 8 + tc * 2;
                uint32_t w0 = (cc < 32) ? mb[mt * 2].x     : mb[mt * 2].y;
                uint32_t w1 = (cc < 32) ? mb[mt * 2 + 1].x : mb[mt * 2 + 1].y;
                int sh = cc & 31;
                float e0 = ((w0 >> sh) & 1u)       ? __expf(acc[mt][nt][0]) : 0.f;
                float e1 = ((w0 >> (sh + 1)) & 1u) ? __expf(acc[mt][nt][1]) : 0.f;
                float e2 = ((w1 >> sh) & 1u)       ? __expf(acc[mt][nt][2]) : 0.f;
                float e3 = ((w1 >> (sh + 1)) & 1u) ? __expf(acc[mt][nt][3]) : 0.f;
                __stcs(reinterpret_cast<float2*>(Eb + (size_t)r * L + cc),       make_float2(e0, e1));
                __stcs(reinterpret_cast<float2*>(Eb + (size_t)(r + 8) * L + cc), make_float2(e2, e3));
                rowsum[mt * 2]     += e0 + e1;
                rowsum[mt * 2 + 1] += e2 + e3;
                cs0[nt] += e0 + e2;
                cs1[nt] += e1 + e3;
            }
#pragma unroll
        for (int nt = 0; nt < 4; nt++) {
            cs0[nt] += __shfl_xor_sync(0xFFFFFFFFu, cs0[nt], 4);
            cs0[nt] += __shfl_xor_sync(0xFFFFFFFFu, cs0[nt], 8);
            cs0[nt] += __shfl_xor_sync(0xFFFFFFFFu, cs0[nt], 16);
            cs1[nt] += __shfl_xor_sync(0xFFFFFFFFu, cs1[nt], 4);
            cs1[nt] += __shfl_xor_sync(0xFFFFFFFFu, cs1[nt], 8);
            cs1[nt] += __shfl_xor_sync(0xFFFFFFFFu, cs1[nt], 16);
        }
#pragma unroll
        for (int nt = 0; nt < 4; nt++) {
            if (tr == nt) {
                int c = jl * 64 + wc * 32 + nt * 8 + tc * 2;
                colacc[wr][c]     += cs0[nt];
                colacc[wr][c + 1] += cs1[nt];
            }
        }
    }

#pragma unroll
    for (int u = 0; u < 4; u++) {
        rowsum[u] += __shfl_xor_sync(0xFFFFFFFFu, rowsum[u], 1);
        rowsum[u] += __shfl_xor_sync(0xFFFFFFFFu, rowsum[u], 2);
    }
    if (tc == 0) {
        float* rp = &g_rps[(size_t)(jt4 * 2 + wc) * BL + (size_t)b * L + i0 + wr * 32 + tr];
        rp[0] = rowsum[0]; rp[8] = rowsum[1]; rp[16] = rowsum[2]; rp[24] = rowsum[3];
    }
    __syncthreads();
    {
        int c = tid * 2;
        float s0 = colacc[0][c] + colacc[1][c] + colacc[2][c] + colacc[3][c];
        float s1 = colacc[0][c + 1] + colacc[1][c + 1] + colacc[2][c + 1] + colacc[3][c + 1];
        float* cp = &g_cps[(size_t)blockIdx.y * BL + (size_t)b * L + jt4 * 512 + c];
        cp[0] = s0; cp[1] = s1;
    }
}

// ============================================================
// K5: prologue merges partials; gated = (E*rdi)*(E*cdi) in place;
// out partial = gated @ v.  grid (16 it, 2 ks, B), block 256, 2 CTAs/SM.
// ks=0 writes directly to out; ks=1 writes g_opart.
// (round-14 best structure)
// ============================================================
__global__ __launch_bounds__(256, 2) void k_gate_out_mma(
    float* __restrict__ Eg, float* __restrict__ out)
{
    extern __shared__ __align__(16) char smem[];
    __shared__ float F_s[128];
    __shared__ float cd_all[1024];

    const int tid = threadIdx.x;
    const int w = tid >> 5, lane = tid & 31;
    const int b = blockIdx.z;
    const int i0 = blockIdx.x * 128;
    const int ks = blockIdx.y;

    const uint32_t bg  = smem_u32(smem);
    const uint32_t bgl = bg + TILEB;
    const uint32_t bv  = bg + 2 * TILEB;
    const uint32_t bvl = bv + VTILE;

    // prologue: merge row/col partials for this CTA's spans
    if (tid < 128) {
        float rs = 0.f;
#pragma unroll
        for (int p = 0; p < 8; p++) rs += g_rps[(size_t)p * BL + (size_t)b * L + i0 + tid];
        F_s[tid] = 1.0f / (rs + EPSV);
    }
#pragma unroll
    for (int u = 0; u < 4; u++) {
        int col = u * 256 + tid;
        float cs = 0.f;
#pragma unroll
        for (int p = 0; p < 16; p++) cs += g_cps[(size_t)p * BL + (size_t)b * L + ks * 1024 + col];
        cd_all[col] = 1.0f / (cs + EPSV);
    }

    const int wr = w & 3, wc = w >> 2;
    const int tr = lane >> 2, tc = lane & 3;
    float acc[2][8][4];
#pragma unroll
    for (int mt = 0; mt < 2; mt++)
#pragma unroll
        for (int nt = 0; nt < 8; nt++)
#pragma unroll
            for (int u = 0; u < 4; u++) acc[mt][nt][u] = 0.f;

    float* Eb = Eg + ((size_t)b * L + i0) * L;
    const __nv_bfloat16* vhB = g_vTh + (size_t)b * D * L;
    const __nv_bfloat16* vlB = g_vTl + (size_t)b * D * L;

    __syncthreads();   // prologue visible

    for (int jc = 0; jc < 8; jc++) {
        const int j0 = ks * 1024 + jc * 128;

        // issue v chunk hc=0 (overlaps gate phase)
#pragma unroll
        for (int u = 0; u < 4; u++) {
            int f = u * 256 + tid;
            int row = f >> 3, c = f & 7;
            uint32_t so = (uint32_t)row * VPITCH + (uint32_t)c * 16;
            CP16(bv  + so, vhB + (size_t)row * L + j0 + c * 8);
            CP16(bvl + so, vlB + (size_t)row * L + j0 + c * 8);
        }
        CP_COMMIT();

        // gate phase: read E (128x128), write gated, split -> smem
#pragma unroll
        for (int it = 0; it < 16; it++) {
            int f = it * 256 + tid;
            int row = f >> 5, c4 = f & 31;
            size_t off = (size_t)row * L + j0 + c4 * 4;
            float4 e = __ldcs(reinterpret_cast<const float4*>(Eb + off));
            float4 cd = *reinterpret_cast<const float4*>(&cd_all[jc * 128 + c4 * 4]);
            float Fi = F_s[row];
            float4 g;
            g.x = (e.x * Fi) * (e.x * cd.x);
            g.y = (e.y * Fi) * (e.y * cd.y);
            g.z = (e.z * Fi) * (e.z * cd.z);
            g.w = (e.w * Fi) * (e.w * cd.w);
            __stcs(reinterpret_cast<float4*>(Eb + off), g);
            uint2 h, l;
            split4(g, h, l);
            uint32_t so = (uint32_t)row * PITCHB + (uint32_t)c4 * 8;
            *reinterpret_cast<uint2*>(smem + so)         = h;
            *reinterpret_cast<uint2*>(smem + TILEB + so) = l;
        }

        for (int hc = 0; hc < 2; hc++) {
            CP_WAIT0();
            __syncthreads();   // v chunk ready + gate writes visible

#pragma unroll
            for (int ksv = 0; ksv < 4; ksv++) {
                uint32_t Ah[2][4], Al[2][4], Bh[4][4], Bl[4][4];
                uint32_t arow = (uint32_t)(wr * 32 + (lane & 15)) * PITCHB
                              + hc * 128 + ksv * 32 + ((lane >> 4) << 4);
#pragma unroll
                for (int mt = 0; mt < 2; mt++) {
                    uint32_t ad = arow + mt * 16 * PITCHB;
                    ldm_x4(Ah[mt], bg  + ad);
                    ldm_x4(Al[mt], bgl + ad);
                }
                uint32_t brow = (uint32_t)(wc * 64 + (lane & 7) + ((lane >> 4) << 3)) * VPITCH
                              + ksv * 32 + (((lane >> 3) & 1) << 4);
#pragma unroll
                for (int ntp = 0; ntp < 4; ntp++) {
                    uint32_t bd = brow + ntp * 16 * VPITCH;
                    ldm_x4(Bh[ntp], bv  + bd);
                    ldm_x4(Bl[ntp], bvl + bd);
                }
#pragma unroll
                for (int mt = 0; mt < 2; mt++)
#pragma unroll
                    for (int ntp = 0; ntp < 4; ntp++) {
                        mma_bf16(acc[mt][2 * ntp],     Ah[mt], &Bh[ntp][0]);
                        mma_bf16(acc[mt][2 * ntp + 1], Ah[mt], &Bh[ntp][2]);
                        mma_bf16(acc[mt][2 * ntp],     Al[mt], &Bh[ntp][0]);
                        mma_bf16(acc[mt][2 * ntp + 1], Al[mt], &Bh[ntp][2]);
                        mma_bf16(acc[mt][2 * ntp],     Ah[mt], &Bl[ntp][0]);
                        mma_bf16(acc[mt][2 * ntp + 1], Ah[mt], &Bl[ntp][2]);
                    }
            }
            __syncthreads();   // v buffer reusable

            if (hc == 0) {     // issue v chunk hc=1
#pragma unroll
                for (int u = 0; u < 4; u++) {
                    int f = u * 256 + tid;
                    int row = f >> 3, c = f & 7;
                    uint32_t so = (uint32_t)row * VPITCH + (uint32_t)c * 16;
                    CP16(bv  + so, vhB + (size_t)row * L + j0 + 64 + c * 8);
                    CP16(bvl + so, vlB + (size_t)row * L + j0 + 64 + c * 8);
                }
                CP_COMMIT();
            }
        }
    }

    // out partial: ks=0 -> out directly, ks=1 -> g_opart
    float* op = (ks == 0) ? (out + ((size_t)b * L + i0) * DV)
                          : (g_opart + ((size_t)b * L + i0) * DV);
#pragma unroll
    for (int mt = 0; mt < 2; mt++)
#pragma unroll
        for (int nt = 0; nt < 8; nt++) {
            int r = wr * 32 + mt * 16 + tr;
            int cc = wc * 64 + nt * 8 + tc * 2;
            *reinterpret_cast<float2*>(op + (size_t)r * DV + cc) =
                make_float2(acc[mt][nt][0], acc[mt][nt][1]);
            *reinterpret_cast<float2*>(op + (size_t)(r + 8) * DV + cc) =
                make_float2(acc[mt][nt][2], acc[mt][nt][3]);
        }
}

// K6: out += ks=1 partial
__global__ __launch_bounds__(256) void k_out_reduce(float* __restrict__ out)
{
    const size_t i = ((size_t)blockIdx.x * 256 + threadIdx.x) * 4;
    float4 a = *reinterpret_cast<const float4*>(out + i);
    float4 bq = *reinterpret_cast<const float4*>(&g_opart[i]);
    float4 r;
    r.x = a.x + bq.x; r.y = a.y + bq.y; r.z = a.z + bq.z; r.w = a.w + bq.w;
    *reinterpret_cast<float4*>(out + i) = r;
}

// ============================================================
extern "C" void kernel_launch(void* const* d_in, const int* in_sizes, int n_in,
                              void* d_out, int out_size)
{
    const float* q    = (const float*)d_in[0];
    const float* kmat = (const float*)d_in[1];
    const float* v    = (const float*)d_in[2];
    const float* mask = (const float*)d_in[3];

    float* out   = (float*)d_out;
    float* gated = out + (size_t)BB * L * DV;   // E -> gated in place

    cudaFuncSetAttribute(k_qkE,          cudaFuncAttributeMaxDynamicSharedMemorySize, SMEM_K1);
    cudaFuncSetAttribute(k_gate_out_mma, cudaFuncAttributeMaxDynamicSharedMemorySize, SMEM_K5);

    k_split_all<<<16384, 256>>>(q, kmat, v, mask);                   // 1
    k_qkE<<<dim3(4, 16, BB), 256, SMEM_K1>>>(gated);                 // 2
    k_gate_out_mma<<<dim3(16, 2, BB), 256, SMEM_K5>>>(gated, out);   // 3
    k_out_reduce<<<(BB * L * DV) / 1024, 256>>>(out);                // 4
}

// round 17
// speedup vs baseline: 1.0568x; 1.0350x over previous
#include <cuda_runtime.h>
#include <cuda_bf16.h>
#include <math.h>
#include <stdint.h>

#define BB 16
#define L  2048
#define D  128
#define DV 128
#define EPSV 1e-12f
#define BL (BB * L)
#define LW (L / 32)

#define PITCHB 272                 // q/k smem row pitch (128 bf16 + pad)
#define TILEB  (128 * PITCHB)      // 34816 B per 128x128 bf16 tile
#define KCHUNKB (64 * PITCHB)      // 17408 B per 64-row k chunk
#define VPITCH 144                 // v chunk row pitch (64 bf16 + pad)
#define VTILE  (128 * VPITCH)      // 18432 B per 128d x 64j v chunk
#define SMEM_K1 (2 * TILEB + 2 * KCHUNKB)   // 104448
#define SMEM_K5 (2 * TILEB + 2 * VTILE)     // 106496

// ---- device scratch ----
__device__ float g_rps[16 * BL];   // row-sum partials (8 jt8-groups x 2 wc)
__device__ float g_cps[16 * BL];   // col-sum partials (16 i-tiles)
__device__ uint32_t g_mbits[(size_t)BB * L * LW];
__device__ __nv_bfloat16 g_qh[BB * L * D], g_ql[BB * L * D];
__device__ __nv_bfloat16 g_kh[BB * L * D], g_kl[BB * L * D];
__device__ __nv_bfloat16 g_vTh[BB * D * L], g_vTl[BB * D * L]; // [b][d][j]
__device__ float g_opart[3 * (size_t)BB * L * DV];   // ks=1..3 partials

// ================= helpers =================
__device__ __forceinline__ uint32_t smem_u32(const void* p) {
    uint32_t a;
    asm("{ .reg .u64 t; cvta.to.shared.u64 t, %1; cvt.u32.u64 %0, t; }" : "=r"(a) : "l"(p));
    return a;
}
__device__ __forceinline__ void ldm_x4(uint32_t* r, uint32_t addr) {
    asm volatile("ldmatrix.sync.aligned.m8n8.x4.shared.b16 {%0,%1,%2,%3}, [%4];"
        : "=r"(r[0]), "=r"(r[1]), "=r"(r[2]), "=r"(r[3]) : "r"(addr));
}
__device__ __forceinline__ void mma_bf16(float* c, const uint32_t* a, const uint32_t* b) {
    asm volatile("mma.sync.aligned.m16n8k16.row.col.f32.bf16.bf16.f32 "
        "{%0,%1,%2,%3}, {%4,%5,%6,%7}, {%8,%9}, {%0,%1,%2,%3};"
        : "+f"(c[0]), "+f"(c[1]), "+f"(c[2]), "+f"(c[3])
        : "r"(a[0]), "r"(a[1]), "r"(a[2]), "r"(a[3]), "r"(b[0]), "r"(b[1]));
}
#define CP16(dst, src) asm volatile("cp.async.cg.shared.global [%0], [%1], 16;" :: "r"(dst), "l"(src))
#define CP_COMMIT()    asm volatile("cp.async.commit_group;" ::: "memory")
#define CP_WAIT0()     asm volatile("cp.async.wait_group 0;" ::: "memory")

__device__ __forceinline__ void split4(float4 a, uint2& h, uint2& l) {
    __nv_bfloat16 h0 = __float2bfloat16(a.x), h1 = __float2bfloat16(a.y);
    __nv_bfloat16 h2 = __float2bfloat16(a.z), h3 = __float2bfloat16(a.w);
    float l0 = a.x - __bfloat162float(h0), l1 = a.y - __bfloat162float(h1);
    float l2 = a.z - __bfloat162float(h2), l3 = a.w - __bfloat162float(h3);
    __nv_bfloat162 ph0{h0, h1}, ph1{h2, h3};
    __nv_bfloat162 pl0{__float2bfloat16(l0), __float2bfloat16(l1)};
    __nv_bfloat162 pl1{__float2bfloat16(l2), __float2bfloat16(l3)};
    h = make_uint2(*reinterpret_cast<uint32_t*>(&ph0), *reinterpret_cast<uint32_t*>(&ph1));
    l = make_uint2(*reinterpret_cast<uint32_t*>(&pl0), *reinterpret_cast<uint32_t*>(&pl1));
}

// ============================================================
// K0: fused split of q,k ; v^T ; mask bitmap.  grid 16384.
// ============================================================
__global__ __launch_bounds__(256) void k_split_all(
    const float* __restrict__ q, const float* __restrict__ kmat,
    const float* __restrict__ v, const float* __restrict__ M)
{
    __shared__ float tile[32][33];
    const int tid = threadIdx.x;
    if (blockIdx.x < 4096) {
        const size_t i = ((size_t)blockIdx.x * 256 + tid) * 4;
        uint2 h, l;
        split4(*reinterpret_cast<const float4*>(q + i), h, l);
        *reinterpret_cast<uint2*>(&g_qh[i]) = h;
        *reinterpret_cast<uint2*>(&g_ql[i]) = l;
        split4(*reinterpret_cast<const float4*>(kmat + i), h, l);
        *reinterpret_cast<uint2*>(&g_kh[i]) = h;
        *reinterpret_cast<uint2*>(&g_kl[i]) = l;
    } else if (blockIdx.x < 8192) {
        const int vb = blockIdx.x - 4096;
        const int jt = vb & 63, dt = (vb >> 6) & 3, b = vb >> 8;
        const int j0 = jt * 32, d0 = dt * 32;
        const int tx = tid & 31, ty = tid >> 5;
#pragma unroll
        for (int i = 0; i < 4; i++)
            tile[ty + i * 8][tx] = v[((size_t)b * L + j0 + ty + i * 8) * DV + d0 + tx];
        __syncthreads();
#pragma unroll
        for (int i = 0; i < 4; i++) {
            float x = tile[tx][ty + i * 8];
            __nv_bfloat16 h = __float2bfloat16(x);
            __nv_bfloat16 lo = __float2bfloat16(x - __bfloat162float(h));
            size_t idx = ((size_t)b * D + d0 + ty + i * 8) * L + j0 + tx;
            g_vTh[idx] = h;
            g_vTl[idx] = lo;
        }
    } else {
        const size_t warpId = ((size_t)(blockIdx.x - 8192) * 256 + tid) >> 5;
        const int lane = tid & 31;
        const size_t base = warpId * 1024;
        uint32_t myword = 0;
#pragma unroll
        for (int i = 0; i < 32; i++) {
            float mv = __ldcs(M + base + (size_t)i * 32 + lane);
            uint32_t bt = __ballot_sync(0xFFFFFFFFu, mv != 0.0f);
            if (lane == i) myword = bt;
        }
        g_mbits[warpId * 32 + lane] = myword;
    }
}

// ============================================================
// K1: fused E = mask*exp(q k^T) + row/col partial sums.
// grid (8 jt8, 16 it, B) = 2048 CTAs, block 256, 2 CTAs/SM,
// 4 chunks of 64 cols per CTA (256-col span).
// ============================================================
__global__ __launch_bounds__(256, 2) void k_qkE(float* __restrict__ E)
{
    extern __shared__ __align__(16) char smem[];
    __shared__ float colacc[4][256];

    const int tid = threadIdx.x;
    const int w = tid >> 5, lane = tid & 31;
    const int b = blockIdx.z;
    const int i0 = blockIdx.y * 128;
    const int jt8 = blockIdx.x;

    const uint32_t bq  = smem_u32(smem);
    const uint32_t bql = bq + TILEB;
    const uint32_t bk  = bq + 2 * TILEB;
    const uint32_t bkl = bk + KCHUNKB;

    const __nv_bfloat16* qh = g_qh + ((size_t)b * L + i0) * D;
    const __nv_bfloat16* ql = g_ql + ((size_t)b * L + i0) * D;
    const __nv_bfloat16* khB = g_kh + (size_t)b * L * D;
    const __nv_bfloat16* klB = g_kl + (size_t)b * L * D;

#pragma unroll
    for (int u = 0; u < 4; u++) ((float*)colacc)[u * 256 + tid] = 0.f;

#pragma unroll
    for (int u = 0; u < 8; u++) {
        int f = u * 256 + tid;
        int row = f >> 4, c = f & 15;
        uint32_t so = (uint32_t)row * PITCHB + (uint32_t)c * 16;
        CP16(bq  + so, qh + (size_t)row * D + c * 8);
        CP16(bql + so, ql + (size_t)row * D + c * 8);
    }
    {
        const int j0 = jt8 * 256;
#pragma unroll
        for (int u = 0; u < 4; u++) {
            int f = u * 256 + tid;
            int row = f >> 4, c = f & 15;
            uint32_t so = (uint32_t)row * PITCHB + (uint32_t)c * 16;
            CP16(bk  + so, khB + ((size_t)(j0 + row)) * D + c * 8);
            CP16(bkl + so, klB + ((size_t)(j0 + row)) * D + c * 8);
        }
    }
    CP_COMMIT();

    const int wr = w & 3, wc = w >> 2;
    const int tr = lane >> 2, tc = lane & 3;
    float rowsum[4] = {0.f, 0.f, 0.f, 0.f};
    const uint32_t* MB = g_mbits + ((size_t)b * L + i0) * LW;

    for (int jl = 0; jl < 4; jl++) {
        const int j0 = jt8 * 256 + jl * 64;
        CP_WAIT0();
        __syncthreads();

        uint2 mb[4];
        {
            const int wbase = j0 >> 5;
#pragma unroll
            for (int u = 0; u < 4; u++) {
                int row = wr * 32 + u * 8 + tr;
                mb[u] = *reinterpret_cast<const uint2*>(MB + (size_t)row * LW + wbase);
            }
        }

        float acc[2][4][4];
#pragma unroll
        for (int mt = 0; mt < 2; mt++)
#pragma unroll
            for (int nt = 0; nt < 4; nt++)
#pragma unroll
                for (int u = 0; u < 4; u++) acc[mt][nt][u] = 0.f;

#pragma unroll
        for (int ks = 0; ks < 8; ks++) {
            const uint32_t kb0 = ks * 32;
            uint32_t Ah[2][4], Al[2][4], Bh[2][4], Bl[2][4];
            uint32_t arow = (uint32_t)(wr * 32 + (lane & 15)) * PITCHB + kb0 + ((lane >> 4) << 4);
#pragma unroll
            for (int mt = 0; mt < 2; mt++) {
                uint32_t ad = arow + mt * 16 * PITCHB;
                ldm_x4(Ah[mt], bq  + ad);
                ldm_x4(Al[mt], bql + ad);
            }
            uint32_t brow = (uint32_t)(wc * 32 + (lane & 7) + ((lane >> 4) << 3)) * PITCHB
                          + kb0 + (((lane >> 3) & 1) << 4);
#pragma unroll
            for (int ntp = 0; ntp < 2; ntp++) {
                uint32_t bd = brow + ntp * 16 * PITCHB;
                ldm_x4(Bh[ntp], bk  + bd);
                ldm_x4(Bl[ntp], bkl + bd);
            }
#pragma unroll
            for (int mt = 0; mt < 2; mt++)
#pragma unroll
                for (int ntp = 0; ntp < 2; ntp++) {
                    mma_bf16(acc[mt][2 * ntp],     Ah[mt], &Bh[ntp][0]);
                    mma_bf16(acc[mt][2 * ntp + 1], Ah[mt], &Bh[ntp][2]);
                    mma_bf16(acc[mt][2 * ntp],     Al[mt], &Bh[ntp][0]);
                    mma_bf16(acc[mt][2 * ntp + 1], Al[mt], &Bh[ntp][2]);
                    mma_bf16(acc[mt][2 * ntp],     Ah[mt], &Bl[ntp][0]);
                    mma_bf16(acc[mt][2 * ntp + 1], Ah[mt], &Bl[ntp][2]);
                }
        }
        __syncthreads();

        if (jl < 3) {
            const int jn = j0 + 64;
#pragma unroll
            for (int u = 0; u < 4; u++) {
                int f = u * 256 + tid;
                int row = f >> 4, c = f & 15;
                uint32_t so = (uint32_t)row * PITCHB + (uint32_t)c * 16;
                CP16(bk  + so, khB + ((size_t)(jn + row)) * D + c * 8);
                CP16(bkl + so, klB + ((size_t)(jn + row)) * D + c * 8);
            }
            CP_COMMIT();
        }

        float* Eb = E + ((size_t)b * L + i0) * L + j0;
        float cs0[4], cs1[4];
#pragma unroll
        for (int nt = 0; nt < 4; nt++) { cs0[nt] = 0.f; cs1[nt] = 0.f; }
#pragma unroll
        for (int mt = 0; mt < 2; mt++)
#pragma unroll
            for (int nt = 0; nt < 4; nt++) {
                int r = wr * 32 + mt * 16 + tr;
                int cc = wc * 32 + nt * 8 + tc * 2;
                uint32_t w0 = (cc < 32) ? mb[mt * 2].x     : mb[mt * 2].y;
                uint32_t w1 = (cc < 32) ? mb[mt * 2 + 1].x : mb[mt * 2 + 1].y;
                int sh = cc & 31;
                float e0 = ((w0 >> sh) & 1u)       ? __expf(acc[mt][nt][0]) : 0.f;
                float e1 = ((w0 >> (sh + 1)) & 1u) ? __expf(acc[mt][nt][1]) : 0.f;
                float e2 = ((w1 >> sh) & 1u)       ? __expf(acc[mt][nt][2]) : 0.f;
                float e3 = ((w1 >> (sh + 1)) & 1u) ? __expf(acc[mt][nt][3]) : 0.f;
                __stcs(reinterpret_cast<float2*>(Eb + (size_t)r * L + cc),       make_float2(e0, e1));
                __stcs(reinterpret_cast<float2*>(Eb + (size_t)(r + 8) * L + cc), make_float2(e2, e3));
                rowsum[mt * 2]     += e0 + e1;
                rowsum[mt * 2 + 1] += e2 + e3;
                cs0[nt] += e0 + e2;
                cs1[nt] += e1 + e3;
            }
#pragma unroll
        for (int nt = 0; nt < 4; nt++) {
            cs0[nt] += __shfl_xor_sync(0xFFFFFFFFu, cs0[nt], 4);
            cs0[nt] += __shfl_xor_sync(0xFFFFFFFFu, cs0[nt], 8);
            cs0[nt] += __shfl_xor_sync(0xFFFFFFFFu, cs0[nt], 16);
            cs1[nt] += __shfl_xor_sync(0xFFFFFFFFu, cs1[nt], 4);
            cs1[nt] += __shfl_xor_sync(0xFFFFFFFFu, cs1[nt], 8);
            cs1[nt] += __shfl_xor_sync(0xFFFFFFFFu, cs1[nt], 16);
        }
#pragma unroll
        for (int nt = 0; nt < 4; nt++) {
            if (tr == nt) {
                int c = jl * 64 + wc * 32 + nt * 8 + tc * 2;
                colacc[wr][c]     += cs0[nt];
                colacc[wr][c + 1] += cs1[nt];
            }
        }
    }

#pragma unroll
    for (int u = 0; u < 4; u++) {
        rowsum[u] += __shfl_xor_sync(0xFFFFFFFFu, rowsum[u], 1);
        rowsum[u] += __shfl_xor_sync(0xFFFFFFFFu, rowsum[u], 2);
    }
    if (tc == 0) {
        float* rp = &g_rps[(size_t)(jt8 * 2 + wc) * BL + (size_t)b * L + i0 + wr * 32 + tr];
        rp[0] = rowsum[0]; rp[8] = rowsum[1]; rp[16] = rowsum[2]; rp[24] = rowsum[3];
    }
    __syncthreads();
    {
        int c = tid;   // one column per thread (256-col window)
        float s = colacc[0][c] + colacc[1][c] + colacc[2][c] + colacc[3][c];
        g_cps[(size_t)blockIdx.y * BL + (size_t)b * L + jt8 * 256 + c] = s;
    }
}

// ============================================================
// K5: prologue merges partials; gated = (E*rdi)*(E*cdi) in place;
// out partial = gated @ v.  grid (16 it, 4 ks, B) = 2048 CTAs,
// block 256, 2 CTAs/SM.  Each CTA covers 512 j-cols (4 jc).
// ks=0 writes out directly; ks=1..3 write g_opart slabs.
// ============================================================
__global__ __launch_bounds__(256, 2) void k_gate_out_mma(
    float* __restrict__ Eg, float* __restrict__ out)
{
    extern __shared__ __align__(16) char smem[];
    __shared__ float F_s[128];
    __shared__ float cd_all[512];

    const int tid = threadIdx.x;
    const int w = tid >> 5, lane = tid & 31;
    const int b = blockIdx.z;
    const int i0 = blockIdx.x * 128;
    const int ks = blockIdx.y;

    const uint32_t bg  = smem_u32(smem);
    const uint32_t bgl = bg + TILEB;
    const uint32_t bv  = bg + 2 * TILEB;
    const uint32_t bvl = bv + VTILE;

    // prologue: merge row/col partials for this CTA's spans
    if (tid < 128) {
        float rs = 0.f;
#pragma unroll
        for (int p = 0; p < 16; p++) rs += g_rps[(size_t)p * BL + (size_t)b * L + i0 + tid];
        F_s[tid] = 1.0f / (rs + EPSV);
    }
#pragma unroll
    for (int u = 0; u < 2; u++) {
        int col = u * 256 + tid;
        float cs = 0.f;
#pragma unroll
        for (int p = 0; p < 16; p++) cs += g_cps[(size_t)p * BL + (size_t)b * L + ks * 512 + col];
        cd_all[col] = 1.0f / (cs + EPSV);
    }

    const int wr = w & 3, wc = w >> 2;
    const int tr = lane >> 2, tc = lane & 3;
    float acc[2][8][4];
#pragma unroll
    for (int mt = 0; mt < 2; mt++)
#pragma unroll
        for (int nt = 0; nt < 8; nt++)
#pragma unroll
            for (int u = 0; u < 4; u++) acc[mt][nt][u] = 0.f;

    float* Eb = Eg + ((size_t)b * L + i0) * L;
    const __nv_bfloat16* vhB = g_vTh + (size_t)b * D * L;
    const __nv_bfloat16* vlB = g_vTl + (size_t)b * D * L;

    __syncthreads();   // prologue visible

    for (int jc = 0; jc < 4; jc++) {
        const int j0 = ks * 512 + jc * 128;

        // issue v chunk hc=0 (overlaps gate phase)
#pragma unroll
        for (int u = 0; u < 4; u++) {
            int f = u * 256 + tid;
            int row = f >> 3, c = f & 7;
            uint32_t so = (uint32_t)row * VPITCH + (uint32_t)c * 16;
            CP16(bv  + so, vhB + (size_t)row * L + j0 + c * 8);
            CP16(bvl + so, vlB + (size_t)row * L + j0 + c * 8);
        }
        CP_COMMIT();

        // gate phase: read E (128x128), write gated, split -> smem
#pragma unroll
        for (int it = 0; it < 16; it++) {
            int f = it * 256 + tid;
            int row = f >> 5, c4 = f & 31;
            size_t off = (size_t)row * L + j0 + c4 * 4;
            float4 e = __ldcs(reinterpret_cast<const float4*>(Eb + off));
            float4 cd = *reinterpret_cast<const float4*>(&cd_all[jc * 128 + c4 * 4]);
            float Fi = F_s[row];
            float4 g;
            g.x = (e.x * Fi) * (e.x * cd.x);
            g.y = (e.y * Fi) * (e.y * cd.y);
            g.z = (e.z * Fi) * (e.z * cd.z);
            g.w = (e.w * Fi) * (e.w * cd.w);
            __stcs(reinterpret_cast<float4*>(Eb + off), g);
            uint2 h, l;
            split4(g, h, l);
            uint32_t so = (uint32_t)row * PITCHB + (uint32_t)c4 * 8;
            *reinterpret_cast<uint2*>(smem + so)         = h;
            *reinterpret_cast<uint2*>(smem + TILEB + so) = l;
        }

        for (int hc = 0; hc < 2; hc++) {
            CP_WAIT0();
            __syncthreads();   // v chunk ready + gate writes visible

#pragma unroll
            for (int ksv = 0; ksv < 4; ksv++) {
                uint32_t Ah[2][4], Al[2][4], Bh[4][4], Bl[4][4];
                uint32_t arow = (uint32_t)(wr * 32 + (lane & 15)) * PITCHB
                              + hc * 128 + ksv * 32 + ((lane >> 4) << 4);
#pragma unroll
                for (int mt = 0; mt < 2; mt++) {
                    uint32_t ad = arow + mt * 16 * PITCHB;
                    ldm_x4(Ah[mt], bg  + ad);
                    ldm_x4(Al[mt], bgl + ad);
                }
                uint32_t brow = (uint32_t)(wc * 64 + (lane & 7) + ((lane >> 4) << 3)) * VPITCH
                              + ksv * 32 + (((lane >> 3) & 1) << 4);
#pragma unroll
                for (int ntp = 0; ntp < 4; ntp++) {
                    uint32_t bd = brow + ntp * 16 * VPITCH;
                    ldm_x4(Bh[ntp], bv  + bd);
                    ldm_x4(Bl[ntp], bvl + bd);
                }
#pragma unroll
                for (int mt = 0; mt < 2; mt++)
#pragma unroll
                    for (int ntp = 0; ntp < 4; ntp++) {
                        mma_bf16(acc[mt][2 * ntp],     Ah[mt], &Bh[ntp][0]);
                        mma_bf16(acc[mt][2 * ntp + 1], Ah[mt], &Bh[ntp][2]);
                        mma_bf16(acc[mt][2 * ntp],     Al[mt], &Bh[ntp][0]);
                        mma_bf16(acc[mt][2 * ntp + 1], Al[mt], &Bh[ntp][2]);
                        mma_bf16(acc[mt][2 * ntp],     Ah[mt], &Bl[ntp][0]);
                        mma_bf16(acc[mt][2 * ntp + 1], Ah[mt], &Bl[ntp][2]);
                    }
            }
            __syncthreads();   // v buffer reusable

            if (hc == 0) {     // issue v chunk hc=1
#pragma unroll
                for (int u = 0; u < 4; u++) {
                    int f = u * 256 + tid;
                    int row = f >> 3, c = f & 7;
                    uint32_t so = (uint32_t)row * VPITCH + (uint32_t)c * 16;
                    CP16(bv  + so, vhB + (size_t)row * L + j0 + 64 + c * 8);
                    CP16(bvl + so, vlB + (size_t)row * L + j0 + 64 + c * 8);
                }
                CP_COMMIT();
            }
        }
    }

    // out partial: ks=0 -> out directly, ks>=1 -> g_opart slab
    float* op = (ks == 0) ? (out + ((size_t)b * L + i0) * DV)
                          : (g_opart + (size_t)(ks - 1) * BB * L * DV + ((size_t)b * L + i0) * DV);
#pragma unroll
    for (int mt = 0; mt < 2; mt++)
#pragma unroll
        for (int nt = 0; nt < 8; nt++) {
            int r = wr * 32 + mt * 16 + tr;
            int cc = wc * 64 + nt * 8 + tc * 2;
            *reinterpret_cast<float2*>(op + (size_t)r * DV + cc) =
                make_float2(acc[mt][nt][0], acc[mt][nt][1]);
            *reinterpret_cast<float2*>(op + (size_t)(r + 8) * DV + cc) =
                make_float2(acc[mt][nt][2], acc[mt][nt][3]);
        }
}

// K6: out += 3 ks partials
__global__ __launch_bounds__(256) void k_out_reduce(float* __restrict__ out)
{
    const size_t i = ((size_t)blockIdx.x * 256 + threadIdx.x) * 4;
    const size_t n = (size_t)BB * L * DV;
    float4 a  = *reinterpret_cast<const float4*>(out + i);
    float4 p1 = *reinterpret_cast<const float4*>(&g_opart[i]);
    float4 p2 = *reinterpret_cast<const float4*>(&g_opart[n + i]);
    float4 p3 = *reinterpret_cast<const float4*>(&g_opart[2 * n + i]);
    float4 r;
    r.x = (a.x + p1.x) + (p2.x + p3.x);
    r.y = (a.y + p1.y) + (p2.y + p3.y);
    r.z = (a.z + p1.z) + (p2.z + p3.z);
    r.w = (a.w + p1.w) + (p2.w + p3.w);
    *reinterpret_cast<float4*>(out + i) = r;
}

// ============================================================
extern "C" void kernel_launch(void* const* d_in, const int* in_sizes, int n_in,
                              void* d_out, int out_size)
{
    const float* q    = (const float*)d_in[0];
    const float* kmat = (const float*)d_in[1];
    const float* v    = (const float*)d_in[2];
    const float* mask = (const float*)d_in[3];

    float* out   = (float*)d_out;
    float* gated = out + (size_t)BB * L * DV;   // E -> gated in place

    cudaFuncSetAttribute(k_qkE,          cudaFuncAttributeMaxDynamicSharedMemorySize, SMEM_K1);
    cudaFuncSetAttribute(k_gate_out_mma, cudaFuncAttributeMaxDynamicSharedMemorySize, SMEM_K5);

    k_split_all<<<16384, 256>>>(q, kmat, v, mask);                   // 1
    k_qkE<<<dim3(8, 16, BB), 256, SMEM_K1>>>(gated);                 // 2
    k_gate_out_mma<<<dim3(16, 4, BB), 256, SMEM_K5>>>(gated, out);   // 3
    k_out_reduce<<<(BB * L * DV) / 1024, 256>>>(out);                // 4
}